// round 11
// baseline (speedup 1.0000x reference)
#include <cuda_runtime.h>

// x: (64, 8, 32, 32) fp32. 1 center + 63 error rows, content = 8192 elements.
// Output = (1 + 63 + 8192) x 8192 = 270 MB.
#define N_CONTENT 8192
#define N_COL4    (N_CONTENT / 4)   // 2048
#define E_ROWS    64
#define NCHUNK    128               // prep blocks; 64 k's per chunk
#define PATCH_BLOCKS (N_CONTENT / 256)   // 32

// Scratch (__device__ globals; zero-initialized at module load)
__device__ float4            g_mult4[N_COL4];
__device__ float4            g_head4[N_COL4];
__device__ float             g_val[N_CONTENT];     // per-k delta/2
__device__ unsigned          g_mask[2 * NCHUNK];   // crossing flags, 64 bits/chunk
__device__ unsigned          g_prepep[NCHUNK];     // prep per-block launch counter
__device__ unsigned          g_patchep[PATCH_BLOCKS];
__device__ unsigned          g_prep_ctr;           // monotone completion count
__device__ volatile unsigned g_done;               // = L once launch L's prep done

// ---------------------------------------------------------------------------
// K1: prep-lite — NO cross-block communication. Reduction, per-k scalars,
//     flag masks, values, then one atomicAdd to publish completion.
// ---------------------------------------------------------------------------
__global__ void prep_kernel(const float* __restrict__ x) {
    cudaTriggerProgrammaticLaunchCompletion();   // fill launches immediately

    __shared__ float    s_err[4][64];
    __shared__ unsigned s_L;

    int t = threadIdx.x;
    int b = blockIdx.x;

    if (t == 0) {                          // replay-safe launch epoch
        unsigned L = g_prepep[b] + 1;
        g_prepep[b] = L;
        s_L = L;
    }

    int kk = t & 63;
    int sl = t >> 6;                       // e-slice 0..3 (16 rows each)
    {
        int k  = b * 64 + kk;
        int e0 = sl * 16 + (sl == 0 ? 1 : 0);   // skip center row
        int e1 = sl * 16 + 16;
        float p = 0.f;
#pragma unroll
        for (int e = e0; e < e1; e++)
            p += fabsf(x[e * N_CONTENT + k]);
        s_err[sl][kk] = p;
    }
    __syncthreads();
    unsigned L = s_L;

    if (t < 64) {                          // warps 0,1 fully active
        int k = b * 64 + t;
        float err = s_err[0][t] + s_err[1][t] + s_err[2][t] + s_err[3][t];
        float c = x[k];

        float upper = c + err;
        float lower = c - err;

        float cross  = (lower * upper < 0.f) ? 1.f : 0.f;
        float nonneg = (lower >= 0.f) ? 1.f : 0.f;

        // Reference-exact: lam = nonneg + cross*upper/(upper-lower), NaN -> 0.5
        float lam = nonneg + cross * (upper / (upper - lower));
        if (isnan(lam)) lam = 0.5f;

        float delta = fmaxf(-lam * lower, (1.f - lam) * upper);

        ((float*)g_mult4)[k] = lam * cross + nonneg;
        ((float*)g_head4)[k] = (delta * 0.5f + lam * c) * cross + c * nonneg;
        g_val[k] = delta * 0.5f;

        int flag = (cross > 0.f) ? 1 : 0;
        unsigned bal = __ballot_sync(0xffffffffu, flag);
        if ((t & 31) == 0) g_mask[b * 2 + (t >> 5)] = bal;
    }
    __syncthreads();

    if (t == 0) {                          // epoch-tagged completion (release)
        __threadfence();
        unsigned done = atomicAdd(&g_prep_ctr, 1u) + 1u;
        if (done == (unsigned)NCHUNK * L)
            g_done = L;
    }
}

// ---------------------------------------------------------------------------
// K2: fill — tail rows FIRST in the grid (bid 0..8191): pure zero streaming,
//     no syncs, retire immediately. Head/body rows are the LAST 64 blocks,
//     scheduled ~36us in, so their gridDepSync on prep is free.
// ---------------------------------------------------------------------------
__global__ void __launch_bounds__(256) fill_kernel(
        const float4* __restrict__ x4, float4* __restrict__ out4) {
    int bid = blockIdx.x;
    int t   = threadIdx.x;

    if (bid < N_CONTENT) {
        // tail row bid
        float4* row = out4 + (long long)(E_ROWS + bid) * N_COL4;
        float4 z = make_float4(0.f, 0.f, 0.f, 0.f);
#pragma unroll
        for (int j = 0; j < 8; j++)
            __stcs(row + (t + j * 256), z);
        return;
    }

    cudaGridDependencySynchronize();        // prep results (expected free: last wave)

    int r = bid - N_CONTENT;                // 0..63
    float4* row = out4 + (long long)r * N_COL4;
    if (r == 0) {
#pragma unroll
        for (int j = 0; j < 8; j++) {
            int c4 = t + j * 256;
            row[c4] = g_head4[c4];
        }
    } else {
        const float4* xr = x4 + (long long)r * N_COL4;
#pragma unroll
        for (int j = 0; j < 8; j++) {
            int c4 = t + j * 256;
            float4 v = xr[c4];              // L2-hot
            float4 m = g_mult4[c4];
            v.x *= m.x; v.y *= m.y; v.z *= m.z; v.w *= m.w;
            row[c4] = v;
        }
    }
}

// ---------------------------------------------------------------------------
// K3: patch — after fill's grid completes, each of 32 blocks re-derives the
//     chunk prefix from g_mask (1 KB, L2-hot) and scatters its 256 rows.
// ---------------------------------------------------------------------------
__global__ void patch_kernel(float4* __restrict__ out4) {
    __shared__ unsigned s_L;
    __shared__ int s_incl[NCHUNK];          // inclusive prefix of chunk counts
    __shared__ int s_wtot[4];

    int t = threadIdx.x;
    int b = blockIdx.x;
    int lane = t & 31;
    int w = t >> 5;

    if (t == 0) {                           // replay-safe epoch
        unsigned L = g_patchep[b] + 1;
        g_patchep[b] = L;
        s_L = L;
    }
    cudaGridDependencySynchronize();        // all fill stores complete + visible
    __syncthreads();
    unsigned L = s_L;
    if (t == 0)
        while (g_done < L) __nanosleep(32); // prep ordering (expected 0 wait)
    __syncthreads();
    __threadfence();                        // acquire prep writes

    // chunk counts + 128-wide prefix (warps 0..3)
    unsigned m0 = 0, m1 = 0;
    int cnt = 0, incl = 0;
    if (t < NCHUNK) {
        m0 = g_mask[2 * t];
        m1 = g_mask[2 * t + 1];
        cnt = __popc(m0) + __popc(m1);
        incl = cnt;
#pragma unroll
        for (int off = 1; off < 32; off <<= 1) {
            int n = __shfl_up_sync(0xffffffffu, incl, off);
            if (lane >= off) incl += n;
        }
        if (lane == 31) s_wtot[w] = incl;
    }
    __syncthreads();
    if (t < NCHUNK) {
        int wo = 0;
#pragma unroll
        for (int w2 = 0; w2 < 4; w2++)
            if (w2 < w) wo += s_wtot[w2];
        s_incl[t] = wo + incl;              // inclusive prefix
    }
    __syncthreads();

    int total = s_incl[NCHUNK - 1];
    int r = b * 256 + t;                    // this thread's tail row
    if (r < total) {
        // binary search: first chunk with incl > r
        int lo = 0, hi = NCHUNK - 1;
#pragma unroll
        for (int it = 0; it < 7; it++) {
            int mid = (lo + hi) >> 1;
            if (s_incl[mid] > r) hi = mid; else lo = mid + 1;
        }
        int c = hi;
        int excl = (c > 0) ? s_incl[c - 1] : 0;
        int i = r - excl;                   // rank within chunk
        unsigned cm0 = g_mask[2 * c], cm1 = g_mask[2 * c + 1];
        int p0 = __popc(cm0);
        int pos = (i < p0) ? (int)__fns(cm0, 0, i + 1)
                           : 32 + (int)__fns(cm1, 0, i - p0 + 1);
        int k = c * 64 + pos;
        float* rowp = (float*)(out4 + (long long)(E_ROWS + r) * N_COL4);
        rowp[k] = g_val[k];
    }
}

// ---------------------------------------------------------------------------
extern "C" void kernel_launch(void* const* d_in, const int* in_sizes, int n_in,
                              void* d_out, int out_size) {
    const float* x = (const float*)d_in[0];
    float* out = (float*)d_out;

    prep_kernel<<<NCHUNK, 256>>>(x);

    cudaLaunchAttribute attr[1];
    attr[0].id = cudaLaunchAttributeProgrammaticStreamSerialization;
    attr[0].val.programmaticStreamSerializationAllowed = 1;

    cudaLaunchConfig_t cfg = {};
    cfg.blockDim = dim3(256, 1, 1);
    cfg.dynamicSmemBytes = 0;
    cfg.stream = 0;
    cfg.attrs = attr;
    cfg.numAttrs = 1;

    cfg.gridDim = dim3(N_CONTENT + E_ROWS, 1, 1);    // 8256 (tail first)
    cudaLaunchKernelEx(&cfg, fill_kernel, (const float4*)x, (float4*)out);

    cfg.gridDim = dim3(PATCH_BLOCKS, 1, 1);          // 32
    cudaLaunchKernelEx(&cfg, patch_kernel, (float4*)out);
}

// round 12
// speedup vs baseline: 1.0120x; 1.0120x over previous
#include <cuda_runtime.h>

// x: (64, 8, 32, 32) fp32. 1 center + 63 error rows, content = 8192 elements.
// Output = (1 + 63 + 8192) x 8192 = 270 MB.
#define N_CONTENT 8192
#define N_COL4    (N_CONTENT / 4)   // 2048
#define E_ROWS    64
#define NCHUNK    128               // prep blocks; 64 k's per chunk

// Scratch (__device__ globals; zero-initialized at module load)
__device__ float4             g_mult4[N_COL4];
__device__ float4             g_head4[N_COL4];
__device__ int                g_col[N_CONTENT];    // tail row r -> column k
__device__ float              g_tval[N_CONTENT];   // tail row r -> delta/2
__device__ int                g_total;             // number of crossings
__device__ unsigned long long g_pub[NCHUNK];       // (epoch<<32)|count
__device__ unsigned           g_prepep[NCHUNK];    // per-block launch counter

// ---------------------------------------------------------------------------
// K1: prep — 128 blocks x 512 threads. 8 threads per k, 8 e-rows each
//     (shfl reduction), then per-k scalars + uncontended polling prefix
//     -> inverse map. Runs alone (fill blocks park at entry sync).
// ---------------------------------------------------------------------------
__global__ void __launch_bounds__(512) prep_kernel(const float* __restrict__ x) {
    cudaTriggerProgrammaticLaunchCompletion();   // fill launches immediately

    __shared__ float    s_err[64];
    __shared__ unsigned s_mask[2];
    __shared__ unsigned s_L;
    __shared__ int      s_excl;

    int t = threadIdx.x;
    int b = blockIdx.x;

    if (t == 0) {                          // replay-safe launch epoch
        unsigned L = g_prepep[b] + 1;
        g_prepep[b] = L;
        s_L = L;
    }

    // 8 threads per k: thread (kl, sl) sums |x[e]| for e in its 8-row slice
    int kl = t >> 3;                       // 0..63
    int sl = t & 7;                        // 0..7
    int k  = b * 64 + kl;
    {
        int e0 = sl * 8 + (sl == 0 ? 1 : 0);    // skip center row
        float p = 0.f;
#pragma unroll
        for (int e = e0; e < sl * 8 + 8; e++)
            p += fabsf(x[e * N_CONTENT + k]);
        // reduce within the 8-lane group (lanes kl%4*8 .. +7 of this warp)
        p += __shfl_xor_sync(0xffffffffu, p, 4);
        p += __shfl_xor_sync(0xffffffffu, p, 2);
        p += __shfl_xor_sync(0xffffffffu, p, 1);
        if (sl == 0) s_err[kl] = p;
    }
    __syncthreads();
    unsigned L = s_L;

    int   flag = 0;
    float val  = 0.f;
    if (t < 64) {                          // warps 0,1 fully active
        int kb = b * 64 + t;
        float err = s_err[t];
        float c = x[kb];

        float upper = c + err;
        float lower = c - err;

        float cross  = (lower * upper < 0.f) ? 1.f : 0.f;
        float nonneg = (lower >= 0.f) ? 1.f : 0.f;

        // Reference-exact: lam = nonneg + cross*upper/(upper-lower), NaN -> 0.5
        float lam = nonneg + cross * (upper / (upper - lower));
        if (isnan(lam)) lam = 0.5f;

        float delta = fmaxf(-lam * lower, (1.f - lam) * upper);

        ((float*)g_mult4)[kb] = lam * cross + nonneg;
        ((float*)g_head4)[kb] = (delta * 0.5f + lam * c) * cross + c * nonneg;

        flag = (cross > 0.f) ? 1 : 0;
        val  = delta * 0.5f;

        unsigned bal = __ballot_sync(0xffffffffu, flag);
        if ((t & 31) == 0) s_mask[t >> 5] = bal;
    }
    __syncthreads();

    int cnt = __popc(s_mask[0]) + __popc(s_mask[1]);

    // publish (epoch, count); uncontended — fill blocks are parked, not storing
    if (t == 0)
        atomicExch(&g_pub[b], ((unsigned long long)L << 32) | (unsigned)cnt);

    // warp 0: sum predecessor counts (32-wide overlapped polling)
    if (t < 32) {
        int sum = 0;
        for (int i = t; i < b; i += 32) {
            unsigned long long w2;
            do {
                w2 = *((volatile unsigned long long*)&g_pub[i]);
            } while ((unsigned)(w2 >> 32) != L);
            sum += (int)(w2 & 0xffffffffu);
        }
#pragma unroll
        for (int off = 16; off > 0; off >>= 1)
            sum += __shfl_down_sync(0xffffffffu, sum, off);
        if (t == 0) s_excl = sum;
    }
    __syncthreads();
    int excl = s_excl;

    if (t < 64 && flag) {
        unsigned m0 = s_mask[0], m1 = s_mask[1];
        int rank = (t < 32) ? __popc(m0 & ((1u << t) - 1u))
                            : __popc(m0) + __popc(m1 & ((1u << (t - 32)) - 1u));
        int r = min(excl + rank, N_CONTENT - 1);   // matches jnp.clip
        g_col[r]  = b * 64 + t;
        g_tval[r] = val;
    }
    if (b == NCHUNK - 1 && t == 0)
        g_total = excl + cnt;
}

// ---------------------------------------------------------------------------
// K2: mega-fill (round-7 proven, 38.7us) — one row per block, entry sync.
//     Tail rows: stream zeros + t0 patch from the prep-built inverse map.
// ---------------------------------------------------------------------------
__global__ void __launch_bounds__(256) fill_kernel(
        const float4* __restrict__ x4, float4* __restrict__ out4) {
    int r = blockIdx.x;
    int t = threadIdx.x;

    cudaGridDependencySynchronize();        // prep results visible from here

    float4* row = out4 + (long long)r * N_COL4;

    if (r == 0) {
#pragma unroll
        for (int j = 0; j < 8; j++) {
            int c4 = t + j * 256;
            row[c4] = g_head4[c4];
        }
        return;
    }
    if (r < E_ROWS) {
        const float4* xr = x4 + (long long)r * N_COL4;
#pragma unroll
        for (int j = 0; j < 8; j++) {
            int c4 = t + j * 256;
            float4 v = xr[c4];              // L2-hot
            float4 m = g_mult4[c4];
            v.x *= m.x; v.y *= m.y; v.z *= m.z; v.w *= m.w;
            row[c4] = v;
        }
        return;
    }

    // tail row
    int tr = r - E_ROWS;
    int   k = -1;
    float v = 0.f;
    if (t == 0 && tr < g_total) {           // loads overlap the stores below
        k = g_col[tr];
        v = g_tval[tr];
    }

    float4 z = make_float4(0.f, 0.f, 0.f, 0.f);
#pragma unroll
    for (int j = 0; j < 8; j++)
        __stcs(row + (t + j * 256), z);
    __syncthreads();                        // order patch after zeros

    if (k >= 0)
        ((float*)row)[k] = v;
}

// ---------------------------------------------------------------------------
extern "C" void kernel_launch(void* const* d_in, const int* in_sizes, int n_in,
                              void* d_out, int out_size) {
    const float* x = (const float*)d_in[0];
    float* out = (float*)d_out;

    prep_kernel<<<NCHUNK, 512>>>(x);

    // PDL: fill's launch/ramp overlaps prep; blocks gate at entry.
    cudaLaunchConfig_t cfg = {};
    cfg.gridDim  = dim3(E_ROWS + N_CONTENT, 1, 1);   // 8256
    cfg.blockDim = dim3(256, 1, 1);
    cfg.dynamicSmemBytes = 0;
    cfg.stream = 0;
    cudaLaunchAttribute attr[1];
    attr[0].id = cudaLaunchAttributeProgrammaticStreamSerialization;
    attr[0].val.programmaticStreamSerializationAllowed = 1;
    cfg.attrs = attr;
    cfg.numAttrs = 1;
    cudaLaunchKernelEx(&cfg, fill_kernel, (const float4*)x, (float4*)out);
}

// round 13
// speedup vs baseline: 1.0128x; 1.0007x over previous
#include <cuda_runtime.h>

// x: (64, 8, 32, 32) fp32. 1 center + 63 error rows, content = 8192 elements.
// Output = (1 + 63 + 8192) x 8192 = 270 MB.
#define N_CONTENT 8192
#define N_COL4    (N_CONTENT / 4)   // 2048
#define E_ROWS    64
#define NCHUNK    128               // prep chunks; 64 k's each
#define TOTAL_BLOCKS (N_CONTENT + E_ROWS)   // 8256
#define PATCH_BLOCKS (N_CONTENT / 256)      // 32

// Scratch (__device__ globals; zero-initialized at module load)
__device__ float4            g_mult4[N_COL4];
__device__ float4            g_head4[N_COL4];
__device__ float             g_val[N_CONTENT];     // per-k delta/2
__device__ unsigned          g_mask[2 * NCHUNK];   // crossing flags, 64 bits/chunk
__device__ unsigned          g_blkep[TOTAL_BLOCKS];// per-block launch counters
__device__ unsigned          g_prep_ctr;           // monotone completion count
__device__ volatile unsigned g_done;               // = L once launch L's prep done

// ---------------------------------------------------------------------------
// K1 (fused): bid 0..8191 = tail rows (bid<128 run prep-lite first), pure
//   zero streaming, no waits. bid 8192..8255 = head/body rows, scheduled
//   last so their wait on g_done is free.
// ---------------------------------------------------------------------------
__global__ void __launch_bounds__(256) fused_kernel(
        const float* __restrict__ x, float4* __restrict__ out4) {
    int bid = blockIdx.x;
    int t   = threadIdx.x;

    if (bid < N_CONTENT) {
        // ============== prep-lite (blocks 0..127 only) ==============
        if (bid < NCHUNK) {
            __shared__ float    s_err[4][64];
            __shared__ unsigned s_L;

            if (t == 0) {                       // replay-safe launch epoch
                unsigned L = g_blkep[bid] + 1;
                g_blkep[bid] = L;
                s_L = L;
            }

            int kk = t & 63;
            int sl = t >> 6;                    // e-slice 0..3 (16 rows each)
            {
                int k  = bid * 64 + kk;
                int e0 = sl * 16 + (sl == 0 ? 1 : 0);   // skip center row
                float p = 0.f;
#pragma unroll
                for (int e = e0; e < sl * 16 + 16; e++)
                    p += fabsf(x[e * N_CONTENT + k]);
                s_err[sl][kk] = p;
            }
            __syncthreads();
            unsigned L = s_L;

            if (t < 64) {                       // warps 0,1 fully active
                int k = bid * 64 + t;
                float err = s_err[0][t] + s_err[1][t] + s_err[2][t] + s_err[3][t];
                float c = x[k];

                float upper = c + err;
                float lower = c - err;

                float cross  = (lower * upper < 0.f) ? 1.f : 0.f;
                float nonneg = (lower >= 0.f) ? 1.f : 0.f;

                // Reference-exact: lam = nonneg + cross*upper/(upper-lower), NaN->0.5
                float lam = nonneg + cross * (upper / (upper - lower));
                if (isnan(lam)) lam = 0.5f;

                float delta = fmaxf(-lam * lower, (1.f - lam) * upper);

                ((float*)g_mult4)[k] = lam * cross + nonneg;
                ((float*)g_head4)[k] = (delta * 0.5f + lam * c) * cross + c * nonneg;
                g_val[k] = delta * 0.5f;

                int flag = (cross > 0.f) ? 1 : 0;
                unsigned bal = __ballot_sync(0xffffffffu, flag);
                if ((t & 31) == 0) g_mask[bid * 2 + (t >> 5)] = bal;
            }
            __syncthreads();

            if (t == 0) {                       // epoch-tagged completion
                __threadfence();
                unsigned done = atomicAdd(&g_prep_ctr, 1u) + 1u;
                if (done == (unsigned)NCHUNK * s_L)
                    g_done = s_L;
            }
        }

        // ============== tail row: pure zero streaming ==============
        float4* row = out4 + (long long)(E_ROWS + bid) * N_COL4;
        float4 z = make_float4(0.f, 0.f, 0.f, 0.f);
#pragma unroll
        for (int j = 0; j < 8; j++)
            __stcs(row + (t + j * 256), z);
        return;
    }

    // ============== head/body rows (last 64 blocks) ==============
    __shared__ unsigned s_L2;
    if (t == 0) {
        unsigned L = g_blkep[bid] + 1;          // replay-safe epoch
        g_blkep[bid] = L;
        s_L2 = L;
        while (g_done < L) __nanosleep(64);     // expected ~0 wait (late wave)
        __threadfence();                        // acquire prep writes
    }
    __syncthreads();

    int r = bid - N_CONTENT;                    // 0..63
    float4* row = out4 + (long long)r * N_COL4;
    if (r == 0) {
#pragma unroll
        for (int j = 0; j < 8; j++) {
            int c4 = t + j * 256;
            row[c4] = g_head4[c4];
        }
    } else {
        const float4* xr = ((const float4*)x) + (long long)r * N_COL4;
#pragma unroll
        for (int j = 0; j < 8; j++) {
            int c4 = t + j * 256;
            float4 v = xr[c4];                  // L2-hot
            float4 m = g_mult4[c4];
            v.x *= m.x; v.y *= m.y; v.z *= m.z; v.w *= m.w;
            row[c4] = v;
        }
    }
}

// ---------------------------------------------------------------------------
// K2: patch — gridDepSync on the fused grid (all zeros + prep complete),
//   then rebuild rank->column from the 1 KB masks and scatter 8192 values.
// ---------------------------------------------------------------------------
__global__ void __launch_bounds__(256) patch_kernel(float4* __restrict__ out4) {
    __shared__ int s_incl[NCHUNK];              // inclusive prefix of chunk counts
    __shared__ int s_wtot[4];

    cudaGridDependencySynchronize();            // fused grid done + visible

    int t = threadIdx.x;
    int b = blockIdx.x;
    int lane = t & 31;
    int w = t >> 5;

    int cnt = 0, incl = 0;
    if (t < NCHUNK) {                           // warps 0..3
        cnt = __popc(g_mask[2 * t]) + __popc(g_mask[2 * t + 1]);
        incl = cnt;
#pragma unroll
        for (int off = 1; off < 32; off <<= 1) {
            int n = __shfl_up_sync(0xffffffffu, incl, off);
            if (lane >= off) incl += n;
        }
        if (lane == 31) s_wtot[w] = incl;
    }
    __syncthreads();
    if (t < NCHUNK) {
        int wo = 0;
#pragma unroll
        for (int w2 = 0; w2 < 4; w2++)
            if (w2 < w) wo += s_wtot[w2];
        s_incl[t] = wo + incl;
    }
    __syncthreads();

    int total = s_incl[NCHUNK - 1];
    int r = b * 256 + t;                        // this thread's tail row
    if (r < total) {
        int lo = 0, hi = NCHUNK - 1;            // first chunk with incl > r
#pragma unroll
        for (int it = 0; it < 7; it++) {
            int mid = (lo + hi) >> 1;
            if (s_incl[mid] > r) hi = mid; else lo = mid + 1;
        }
        int c = hi;
        int excl = (c > 0) ? s_incl[c - 1] : 0;
        int i = r - excl;                       // rank within chunk
        unsigned cm0 = g_mask[2 * c], cm1 = g_mask[2 * c + 1];
        int p0 = __popc(cm0);
        int pos = (i < p0) ? (int)__fns(cm0, 0, i + 1)
                           : 32 + (int)__fns(cm1, 0, i - p0 + 1);
        int k = c * 64 + pos;                   // (r never exceeds 8191: matches clip)
        float* rowp = (float*)(out4 + (long long)(E_ROWS + r) * N_COL4);
        rowp[k] = g_val[k];
    }
}

// ---------------------------------------------------------------------------
extern "C" void kernel_launch(void* const* d_in, const int* in_sizes, int n_in,
                              void* d_out, int out_size) {
    const float* x = (const float*)d_in[0];
    float* out = (float*)d_out;

    fused_kernel<<<TOTAL_BLOCKS, 256>>>(x, (float4*)out);

    // patch gated on the fused grid via PDL grid dependency
    cudaLaunchConfig_t cfg = {};
    cfg.gridDim  = dim3(PATCH_BLOCKS, 1, 1);
    cfg.blockDim = dim3(256, 1, 1);
    cfg.dynamicSmemBytes = 0;
    cfg.stream = 0;
    cudaLaunchAttribute attr[1];
    attr[0].id = cudaLaunchAttributeProgrammaticStreamSerialization;
    attr[0].val.programmaticStreamSerializationAllowed = 1;
    cfg.attrs = attr;
    cfg.numAttrs = 1;
    cudaLaunchKernelEx(&cfg, patch_kernel, (float4*)out);
}